// round 10
// baseline (speedup 1.0000x reference)
#include <cuda_runtime.h>
#include <math.h>

#define GAMMA 0.99f
#define LAM   0.95f
#define GL    (GAMMA * LAM)
#define EPSN  1e-8

#define CHUNKS 64
#define TPB    256
#define COLS_PER_BLK 16
#define MAXB   1024

// Static device scratch (no allocations). Zero-initialized.
__device__ double   g_part[2 * MAXB];
__device__ unsigned g_cpre;    // rendezvous counter (reset by last block each run)
__device__ unsigned g_rel;     // monotonic release epoch (never reset)
__device__ float    g_mean;
__device__ float    g_inv;     // 1 / (std + eps)

__device__ __forceinline__ unsigned vld(const unsigned* p) {
    return *(const volatile unsigned*)p;
}

// ---------------------------------------------------------------------------
// ONE kernel, one wave. Block b owns columns [16b, 16b+16) for ALL T.
// Thread layout: threadIdx.x = cc*4 + q  (cc = chunk 0..63, q = col-quad 0..3).
//
// Part A : compose reverse recurrence over this thread's chunk/4 cols into
//          a_out = D + C*a_in; {C,D} -> SMEM, stats -> SMEM stash.
// sync   : __syncthreads (block-local!).
// Scan   : threads 0..15 reverse-scan their own column's 64 chunk summaries
//          in SMEM -> carries in SMEM. No global traffic, no grid barrier.
// Stats  : closed-form per-chunk sum/sumsq from stash + carry; block reduce
//          (double); post partial; LAST block reduces all partials in fixed
//          order -> mean, 1/(std+eps); bumps epoch. All blocks wait on epoch
//          (this is the single, unavoidable global rendezvous).
// Part C : replay recurrence with carry; write normalized adv + returns.
// ---------------------------------------------------------------------------
__global__ __launch_bounds__(TPB, 4)
void gae_one(const float* __restrict__ rw, const float* __restrict__ val,
             const int* __restrict__ dn, float* __restrict__ adv,
             float* __restrict__ ret, int N, int L, long long M) {
    const unsigned nb = gridDim.x;
    const int q   = threadIdx.x & 3;
    const int cc  = threadIdx.x >> 2;          // chunk 0..63
    const int col = blockIdx.x * COLS_PER_BLK + (q << 2);
    const int t0  = cc * L;
    const int t1  = t0 + L - 1;
    const int lc  = q << 2;                    // local col base 0,4,8,12

    __shared__ float2 s_CD[CHUNKS][COLS_PER_BLK];     // 8 KB
    __shared__ float  s_carry[CHUNKS][COLS_PER_BLK];  // 4 KB
    __shared__ float  s_st[20][TPB];                  // 20 KB stat stash
    __shared__ double ss[TPB];                        // 2 KB
    __shared__ double ss2[TPB];                       // 2 KB

    // ---- Part A ----
    {
        float C[4]  = {1.f, 1.f, 1.f, 1.f};
        float D[4]  = {0.f, 0.f, 0.f, 0.f};
        float S1[4] = {0.f, 0.f, 0.f, 0.f};
        float SC[4] = {0.f, 0.f, 0.f, 0.f};
        float S2[4] = {0.f, 0.f, 0.f, 0.f};
        float SDC[4]= {0.f, 0.f, 0.f, 0.f};
        float SC2[4]= {0.f, 0.f, 0.f, 0.f};

        float4 vn = *reinterpret_cast<const float4*>(val + (size_t)(t1 + 1) * N + col);
        #pragma unroll 4
        for (int t = t1; t >= t0; --t) {
            float4 r  = *reinterpret_cast<const float4*>(rw + (size_t)t * N + col);
            int4   dd = *reinterpret_cast<const int4*>(dn + (size_t)t * N + col);
            float4 vc = *reinterpret_cast<const float4*>(val + (size_t)t * N + col);

            float rr[4] = {r.x, r.y, r.z, r.w};
            float vv[4] = {vc.x, vc.y, vc.z, vc.w};
            float vnn[4]= {vn.x, vn.y, vn.z, vn.w};
            int   di[4] = {dd.x, dd.y, dd.z, dd.w};

            #pragma unroll
            for (int j = 0; j < 4; ++j) {
                float nt  = di[j] ? 0.f : 1.f;
                float del = fmaf(GAMMA * nt, vnn[j], rr[j]) - vv[j];
                float cf  = GL * nt;
                D[j] = fmaf(cf, D[j], del);
                C[j] *= cf;
                S1[j] += D[j];
                SC[j] += C[j];
                S2[j]  = fmaf(D[j], D[j], S2[j]);
                SDC[j] = fmaf(D[j], C[j], SDC[j]);
                SC2[j] = fmaf(C[j], C[j], SC2[j]);
            }
            vn = vc;
        }
        #pragma unroll
        for (int j = 0; j < 4; ++j) {
            s_CD[cc][lc + j] = make_float2(C[j], D[j]);
            s_st[j     ][threadIdx.x] = S1[j];
            s_st[j + 4 ][threadIdx.x] = SC[j];
            s_st[j + 8 ][threadIdx.x] = S2[j];
            s_st[j + 12][threadIdx.x] = SDC[j];
            s_st[j + 16][threadIdx.x] = SC2[j];
        }
    }
    __syncthreads();

    // ---- Block-local scan: threads 0..15, one column each ----
    if (threadIdx.x < COLS_PER_BLK) {
        int j = threadIdx.x;
        float a = 0.f;
        #pragma unroll 8
        for (int k = CHUNKS - 1; k >= 0; --k) {
            s_carry[k][j] = a;
            float2 cd = s_CD[k][j];
            a = fmaf(cd.x, a, cd.y);
        }
    }
    __syncthreads();

    // ---- Stats from stash + carries ----
    float ts = 0.f, ts2 = 0.f;
    float a4[4];
    #pragma unroll
    for (int j = 0; j < 4; ++j) {
        float a   = s_carry[cc][lc + j];
        float S1  = s_st[j     ][threadIdx.x];
        float SC  = s_st[j + 4 ][threadIdx.x];
        float S2  = s_st[j + 8 ][threadIdx.x];
        float SDC = s_st[j + 12][threadIdx.x];
        float SC2 = s_st[j + 16][threadIdx.x];
        a4[j] = a;
        ts  += fmaf(SC, a, S1);
        ts2 += fmaf(fmaf(SC2, a, 2.f * SDC), a, S2);
    }
    ss[threadIdx.x]  = (double)ts;
    ss2[threadIdx.x] = (double)ts2;
    __syncthreads();
    for (int st = TPB / 2; st > 0; st >>= 1) {
        if (threadIdx.x < st) {
            ss[threadIdx.x]  += ss[threadIdx.x + st];
            ss2[threadIdx.x] += ss2[threadIdx.x + st];
        }
        __syncthreads();
    }

    __shared__ unsigned s_snap;
    __shared__ bool     s_last;
    if (threadIdx.x == 0) {
        g_part[2 * blockIdx.x]     = ss[0];
        g_part[2 * blockIdx.x + 1] = ss2[0];
        s_snap = vld(&g_rel);               // snapshot BEFORE arrival
        __threadfence();
        unsigned old = atomicAdd(&g_cpre, 1u);
        s_last = (old == nb - 1u);
    }
    __syncthreads();

    if (s_last) {                            // fixed-order final reduce
        double s = 0.0, s2 = 0.0;
        for (int i = threadIdx.x; i < (int)nb; i += TPB) {
            s  += g_part[2 * i];
            s2 += g_part[2 * i + 1];
        }
        ss[threadIdx.x]  = s;
        ss2[threadIdx.x] = s2;
        __syncthreads();
        for (int st = TPB / 2; st > 0; st >>= 1) {
            if (threadIdx.x < st) {
                ss[threadIdx.x]  += ss[threadIdx.x + st];
                ss2[threadIdx.x] += ss2[threadIdx.x + st];
            }
            __syncthreads();
        }
        if (threadIdx.x == 0) {
            double mean = ss[0] / (double)M;
            double var  = (ss2[0] - ss[0] * ss[0] / (double)M) / (double)(M - 1);
            if (var < 0.0) var = 0.0;
            g_mean = (float)mean;
            g_inv  = (float)(1.0 / (sqrt(var) + EPSN));
            g_cpre = 0u;                     // safe: all arrived
            __threadfence();
            atomicAdd(&g_rel, 1u);           // release
        }
    }
    if (threadIdx.x == 0) {
        while (vld(&g_rel) == s_snap) __nanosleep(64);
        __threadfence();
    }
    __syncthreads();

    // ---- Part C: write pass ----
    {
        float m   = g_mean;
        float inv = g_inv;
        float4 a  = make_float4(a4[0], a4[1], a4[2], a4[3]);
        float4 vn = *reinterpret_cast<const float4*>(val + (size_t)(t1 + 1) * N + col);

        #pragma unroll 4
        for (int t = t1; t >= t0; --t) {
            float4 r  = *reinterpret_cast<const float4*>(rw + (size_t)t * N + col);
            int4   dd = *reinterpret_cast<const int4*>(dn + (size_t)t * N + col);
            float4 vc = *reinterpret_cast<const float4*>(val + (size_t)t * N + col);

            float nt, del;
            nt = dd.x ? 0.f : 1.f; del = fmaf(GAMMA * nt, vn.x, r.x) - vc.x;
            a.x = fmaf(GL * nt, a.x, del);
            nt = dd.y ? 0.f : 1.f; del = fmaf(GAMMA * nt, vn.y, r.y) - vc.y;
            a.y = fmaf(GL * nt, a.y, del);
            nt = dd.z ? 0.f : 1.f; del = fmaf(GAMMA * nt, vn.z, r.z) - vc.z;
            a.z = fmaf(GL * nt, a.z, del);
            nt = dd.w ? 0.f : 1.f; del = fmaf(GAMMA * nt, vn.w, r.w) - vc.w;
            a.w = fmaf(GL * nt, a.w, del);

            size_t o = (size_t)t * N + col;
            *reinterpret_cast<float4*>(adv + o) =
                make_float4((a.x - m) * inv, (a.y - m) * inv,
                            (a.z - m) * inv, (a.w - m) * inv);
            *reinterpret_cast<float4*>(ret + o) =
                make_float4(a.x + vc.x, a.y + vc.y, a.z + vc.z, a.w + vc.w);

            vn = vc;
        }
    }
}

extern "C" void kernel_launch(void* const* d_in, const int* in_sizes, int n_in,
                              void* d_out, int out_size) {
    const float* rw  = (const float*)d_in[0];   // rewards [T, N]
    const float* val = (const float*)d_in[1];   // values  [T+1, N]
    const int*   dn  = (const int*)d_in[2];     // dones   [T, N]
    float* out = (float*)d_out;                 // [adv_norm TN | returns TN]

    int TN = in_sizes[0];
    int N  = in_sizes[1] - in_sizes[0];
    int T  = TN / N;
    int L  = T / CHUNKS;

    int blocks = N / COLS_PER_BLK;              // 512 for N=8192 (single wave)

    float* adv = out;
    float* ret = out + (size_t)TN;

    gae_one<<<blocks, TPB>>>(rw, val, dn, adv, ret, N, L, (long long)TN);
}

// round 11
// speedup vs baseline: 1.3145x; 1.3145x over previous
#include <cuda_runtime.h>
#include <math.h>

#define GAMMA 0.99f
#define LAM   0.95f
#define GL    (GAMMA * LAM)
#define EPSN  1e-8

#define CHUNKS 64
#define MAXN   8192
#define TPB    256
#define MAXB   1024

// Static device scratch (no allocations). Zero-initialized.
__device__ float2   g_CD[CHUNKS * MAXN];     // {C, D} 4 MB
__device__ float    g_carry[CHUNKS * MAXN];  // 2 MB
__device__ double   g_part[2 * MAXB];
__device__ unsigned g_c0, g_c1, g_c2;        // barrier counters (last block resets)
__device__ float    g_mean;
__device__ float    g_inv;                   // 1 / (std + eps)

__device__ __forceinline__ unsigned vld(const unsigned* p) {
    return *(const volatile unsigned*)p;
}

// ---------------------------------------------------------------------------
// K1: proven phase1 (per (chunk, 4-col) thread: compose a_out = D + C*a_in,
// register stats) + rendezvous tail:
//   bar0 -> distributed scan (16 cols/block over L2-resident CD) -> bar1 ->
//   stats from smem stash + carries -> post partial -> last block reduces in
//   fixed order -> mean, 1/(std+eps); resets counters. Non-last blocks EXIT
//   immediately after posting (no release wait needed in K1).
// ---------------------------------------------------------------------------
__global__ __launch_bounds__(TPB, 4)
void gae_k1(const float* __restrict__ rw, const float* __restrict__ val,
            const int* __restrict__ dn, int N, int L, long long M) {
    const int groups = N >> 2;
    const unsigned nb = gridDim.x;
    const int tid = blockIdx.x * TPB + threadIdx.x;
    const int c   = tid / groups;
    const int g   = tid - c * groups;
    const int col = g << 2;
    const int t0  = c * L;
    const int t1  = t0 + L - 1;

    __shared__ float  s_st[20][TPB];   // stash: S1,SC,S2,SDC,SC2 x4  (20 KB)
    __shared__ double ss[TPB];
    __shared__ double ss2[TPB];

    // ---- phase1 body (proven) ----
    {
        float C[4]  = {1.f, 1.f, 1.f, 1.f};
        float D[4]  = {0.f, 0.f, 0.f, 0.f};
        float S1[4] = {0.f, 0.f, 0.f, 0.f};
        float SC[4] = {0.f, 0.f, 0.f, 0.f};
        float S2[4] = {0.f, 0.f, 0.f, 0.f};
        float SDC[4]= {0.f, 0.f, 0.f, 0.f};
        float SC2[4]= {0.f, 0.f, 0.f, 0.f};

        float4 vn = *reinterpret_cast<const float4*>(val + (size_t)(t1 + 1) * N + col);
        #pragma unroll 4
        for (int t = t1; t >= t0; --t) {
            float4 r  = *reinterpret_cast<const float4*>(rw + (size_t)t * N + col);
            int4   dd = *reinterpret_cast<const int4*>(dn + (size_t)t * N + col);
            float4 vc = *reinterpret_cast<const float4*>(val + (size_t)t * N + col);

            float rr[4] = {r.x, r.y, r.z, r.w};
            float vv[4] = {vc.x, vc.y, vc.z, vc.w};
            float vnn[4]= {vn.x, vn.y, vn.z, vn.w};
            int   di[4] = {dd.x, dd.y, dd.z, dd.w};

            #pragma unroll
            for (int j = 0; j < 4; ++j) {
                float nt  = di[j] ? 0.f : 1.f;
                float del = fmaf(GAMMA * nt, vnn[j], rr[j]) - vv[j];
                float cf  = GL * nt;
                D[j] = fmaf(cf, D[j], del);
                C[j] *= cf;
                S1[j] += D[j];
                SC[j] += C[j];
                S2[j]  = fmaf(D[j], D[j], S2[j]);
                SDC[j] = fmaf(D[j], C[j], SDC[j]);
                SC2[j] = fmaf(C[j], C[j], SC2[j]);
            }
            vn = vc;
        }
        size_t o = (size_t)c * N + col;
        #pragma unroll
        for (int j = 0; j < 4; ++j) {
            g_CD[o + j] = make_float2(C[j], D[j]);
            s_st[j     ][threadIdx.x] = S1[j];
            s_st[j + 4 ][threadIdx.x] = SC[j];
            s_st[j + 8 ][threadIdx.x] = S2[j];
            s_st[j + 12][threadIdx.x] = SDC[j];
            s_st[j + 16][threadIdx.x] = SC2[j];
        }
    }

    // ---- bar0: CD visible everywhere ----
    __threadfence();
    __syncthreads();
    if (threadIdx.x == 0) {
        atomicAdd(&g_c0, 1u);
        while (vld(&g_c0) < nb) __nanosleep(64);
        __threadfence();
    }
    __syncthreads();

    // ---- distributed scan: 16 cols per block (L2-resident CD) ----
    {
        int colw = blockIdx.x * 16 + threadIdx.x;
        if (threadIdx.x < 16 && colw < N) {
            float a = 0.f;
            #pragma unroll 8
            for (int cc = CHUNKS - 1; cc >= 0; --cc) {
                size_t o = (size_t)cc * N + colw;
                g_carry[o] = a;
                float2 cd = g_CD[o];
                a = fmaf(cd.x, a, cd.y);
            }
        }
    }

    // ---- bar1: carries visible everywhere ----
    __threadfence();
    if (threadIdx.x == 0) {
        atomicAdd(&g_c1, 1u);
        while (vld(&g_c1) < nb) __nanosleep(64);
        __threadfence();
    }
    __syncthreads();

    // ---- stats: closed forms from stash + own carries ----
    float ts = 0.f, ts2 = 0.f;
    {
        size_t o = (size_t)c * N + col;
        #pragma unroll
        for (int j = 0; j < 4; ++j) {
            float a   = g_carry[o + j];
            float S1  = s_st[j     ][threadIdx.x];
            float SC  = s_st[j + 4 ][threadIdx.x];
            float S2  = s_st[j + 8 ][threadIdx.x];
            float SDC = s_st[j + 12][threadIdx.x];
            float SC2 = s_st[j + 16][threadIdx.x];
            ts  += fmaf(SC, a, S1);
            ts2 += fmaf(fmaf(SC2, a, 2.f * SDC), a, S2);
        }
    }
    ss[threadIdx.x]  = (double)ts;
    ss2[threadIdx.x] = (double)ts2;
    __syncthreads();
    for (int st = TPB / 2; st > 0; st >>= 1) {
        if (threadIdx.x < st) {
            ss[threadIdx.x]  += ss[threadIdx.x + st];
            ss2[threadIdx.x] += ss2[threadIdx.x + st];
        }
        __syncthreads();
    }

    __shared__ bool s_last;
    if (threadIdx.x == 0) {
        g_part[2 * blockIdx.x]     = ss[0];
        g_part[2 * blockIdx.x + 1] = ss2[0];
        __threadfence();
        unsigned old = atomicAdd(&g_c2, 1u);
        s_last = (old == nb - 1u);
    }
    __syncthreads();
    if (!s_last) return;                 // non-last blocks exit; no release wait

    // ---- last block: fixed-order final reduce ----
    double s = 0.0, s2 = 0.0;
    for (int i = threadIdx.x; i < (int)nb; i += TPB) {
        s  += g_part[2 * i];
        s2 += g_part[2 * i + 1];
    }
    ss[threadIdx.x]  = s;
    ss2[threadIdx.x] = s2;
    __syncthreads();
    for (int st = TPB / 2; st > 0; st >>= 1) {
        if (threadIdx.x < st) {
            ss[threadIdx.x]  += ss[threadIdx.x + st];
            ss2[threadIdx.x] += ss2[threadIdx.x + st];
        }
        __syncthreads();
    }
    if (threadIdx.x == 0) {
        double mean = ss[0] / (double)M;
        double var  = (ss2[0] - ss[0] * ss[0] / (double)M) / (double)(M - 1);
        if (var < 0.0) var = 0.0;
        g_mean = (float)mean;
        g_inv  = (float)(1.0 / (sqrt(var) + EPSN));
        g_c0 = 0u;  g_c1 = 0u;  g_c2 = 0u;   // safe: all blocks passed/exited
        __threadfence();
    }
}

// ---------------------------------------------------------------------------
// K2: proven write pass (untouched 50.1us / ~6.4 TB/s idiom).
// ---------------------------------------------------------------------------
__global__ __launch_bounds__(TPB)
void gae_write(const float* __restrict__ rw, const float* __restrict__ val,
               const int* __restrict__ dn, float* __restrict__ adv,
               float* __restrict__ ret, int N, int L) {
    int groups = N >> 2;
    int tid = blockIdx.x * blockDim.x + threadIdx.x;
    if (tid >= CHUNKS * groups) return;
    int c   = tid / groups;
    int g   = tid - c * groups;
    int col = g << 2;
    int t0  = c * L;
    int t1  = t0 + L - 1;

    float m   = g_mean;
    float inv = g_inv;

    float4 a  = *reinterpret_cast<const float4*>(g_carry + (size_t)c * N + col);
    float4 vn = *reinterpret_cast<const float4*>(val + (size_t)(t1 + 1) * N + col);

    #pragma unroll 4
    for (int t = t1; t >= t0; --t) {
        float4 r  = *reinterpret_cast<const float4*>(rw + (size_t)t * N + col);
        int4   dd = *reinterpret_cast<const int4*>(dn + (size_t)t * N + col);
        float4 vc = *reinterpret_cast<const float4*>(val + (size_t)t * N + col);

        float nt, del;
        nt = dd.x ? 0.f : 1.f; del = fmaf(GAMMA * nt, vn.x, r.x) - vc.x;
        a.x = fmaf(GL * nt, a.x, del);
        nt = dd.y ? 0.f : 1.f; del = fmaf(GAMMA * nt, vn.y, r.y) - vc.y;
        a.y = fmaf(GL * nt, a.y, del);
        nt = dd.z ? 0.f : 1.f; del = fmaf(GAMMA * nt, vn.z, r.z) - vc.z;
        a.z = fmaf(GL * nt, a.z, del);
        nt = dd.w ? 0.f : 1.f; del = fmaf(GAMMA * nt, vn.w, r.w) - vc.w;
        a.w = fmaf(GL * nt, a.w, del);

        size_t o = (size_t)t * N + col;
        *reinterpret_cast<float4*>(adv + o) =
            make_float4((a.x - m) * inv, (a.y - m) * inv,
                        (a.z - m) * inv, (a.w - m) * inv);
        *reinterpret_cast<float4*>(ret + o) =
            make_float4(a.x + vc.x, a.y + vc.y, a.z + vc.z, a.w + vc.w);

        vn = vc;
    }
}

extern "C" void kernel_launch(void* const* d_in, const int* in_sizes, int n_in,
                              void* d_out, int out_size) {
    const float* rw  = (const float*)d_in[0];   // rewards [T, N]
    const float* val = (const float*)d_in[1];   // values  [T+1, N]
    const int*   dn  = (const int*)d_in[2];     // dones   [T, N]
    float* out = (float*)d_out;                 // [adv_norm TN | returns TN]

    int TN = in_sizes[0];
    int N  = in_sizes[1] - in_sizes[0];
    int T  = TN / N;
    int L  = T / CHUNKS;

    int groups = N >> 2;
    int blocks = (CHUNKS * groups + TPB - 1) / TPB;   // 512: single wave

    float* adv = out;
    float* ret = out + (size_t)TN;

    gae_k1<<<blocks, TPB>>>(rw, val, dn, N, L, (long long)TN);
    gae_write<<<blocks, TPB>>>(rw, val, dn, adv, ret, N, L);
}